// round 9
// baseline (speedup 1.0000x reference)
#include <cuda_runtime.h>

typedef unsigned long long ull;

// Problem: X[8,256,128], W1[128,128], W2[128,128], v[128] -> out[8,256,256]
#define BB   8
#define DD   256
#define DIM  128

// Scratch:
//  g_Ea  : [b*DD+d][m]  natural row-major (k2 stages rows coalesced)
//  g_Ec4 : [b][g=m/4][k][m%4]  (k2 streams float4 per m-quad per thread)
__device__ float g_Ea [BB * DD * DIM];
__device__ float g_Ec4[BB * 32 * DD * 4 + 8192];   // padded for prefetch tail
__device__ float g_Vsum;

// ---- packed f32x2 helpers (Blackwell) --------------------------------------
__device__ __forceinline__ ull fma2(ull a, ull b, ull c) {
    ull d; asm("fma.rn.f32x2 %0,%1,%2,%3;" : "=l"(d) : "l"(a), "l"(b), "l"(c)); return d;
}
__device__ __forceinline__ ull mul2(ull a, ull b) {
    ull d; asm("mul.rn.f32x2 %0,%1,%2;" : "=l"(d) : "l"(a), "l"(b)); return d;
}
__device__ __forceinline__ ull dup2(float x) {
    ull d; asm("mov.b64 %0,{%1,%1};" : "=l"(d) : "f"(x)); return d;
}
__device__ __forceinline__ float2 unpk(ull a) {
    float2 r; asm("mov.b64 {%0,%1},%2;" : "=f"(r.x), "=f"(r.y) : "l"(a)); return r;
}
__device__ __forceinline__ ull pk(float x, float y) {
    ull d; asm("mov.b64 %0,{%1,%2};" : "=l"(d) : "f"(x), "f"(y)); return d;
}
__device__ __forceinline__ float frcp(float x) {
    float r; asm("rcp.approx.f32 %0,%1;" : "=f"(r) : "f"(x)); return r;
}

// ---------------------------------------------------------------------------
// Kernel 1: grid = 128 (64 tiles of 32 rows x 2 mats), 512 threads, 1/SM.
// FFMA2 main loop. mat 0: Ea stored row-major DIRECT (coalesced, no
// transpose). mat 1: Ec via conflict-free smem transpose -> STG.128.
// Block 0 also computes g_Vsum.
// ---------------------------------------------------------------------------
#define W_STRIDE 132
#define K1_SMEM ((DIM * W_STRIDE + 32 * DIM) * 4)

__global__ void __launch_bounds__(512, 1) k1_gemm_exp(
    const float* __restrict__ X,
    const float* __restrict__ W1,
    const float* __restrict__ W2,
    const float* __restrict__ v)
{
    extern __shared__ float sm[];
    float* Ws = sm;                        // 128 x 132 (reused as Es for mat 1)
    float* Xs = sm + DIM * W_STRIDE;       // 32 x 128

    const int t       = threadIdx.x;
    const int mat     = blockIdx.x & 1;
    const int rowbase = (blockIdx.x >> 1) * 32;
    const float* W = mat ? W2 : W1;

    if (blockIdx.x == 0 && t < 32) {       // Vsum side-job
        float s = v[t] + v[t + 32] + v[t + 64] + v[t + 96];
        #pragma unroll
        for (int o = 16; o; o >>= 1) s += __shfl_xor_sync(0xffffffffu, s, o);
        if (t == 0) g_Vsum = s;
    }

    #pragma unroll
    for (int i = t; i < DIM * 32; i += 512) {
        int m  = i >> 5;
        int k4 = i & 31;
        *(float4*)&Ws[m * W_STRIDE + k4 * 4] = ((const float4*)W)[i];
    }
    #pragma unroll
    for (int i = t; i < 1024; i += 512)
        ((float4*)Xs)[i] = ((const float4*)X)[rowbase * 32 + i];
    __syncthreads();

    const int m  = t & 127;
    const int r0 = (t >> 7) * 8;

    ull acc[8];
    #pragma unroll
    for (int r = 0; r < 8; r++) acc[r] = dup2(0.0f);

    #pragma unroll 4
    for (int k4 = 0; k4 < 32; k4++) {
        ulonglong2 w = *(const ulonglong2*)&Ws[m * W_STRIDE + k4 * 4];
        #pragma unroll
        for (int r = 0; r < 8; r++) {
            ulonglong2 x = *(const ulonglong2*)&Xs[(r0 + r) * DIM + k4 * 4];
            acc[r] = fma2(w.x, x.x, acc[r]);
            acc[r] = fma2(w.y, x.y, acc[r]);
        }
    }

    float val[8];
    #pragma unroll
    for (int r = 0; r < 8; r++) {
        float2 a = unpk(acc[r]);
        val[r] = __expf(2.0f * (a.x + a.y));
    }

    cudaTriggerProgrammaticLaunchCompletion();

    const int b  = rowbase >> 8;
    const int d0 = rowbase & 255;

    if (mat == 0) {
        // natural row-major, lanes m consecutive -> coalesced STG.32
        #pragma unroll
        for (int r = 0; r < 8; r++)
            g_Ea[(size_t)(rowbase + r0 + r) * DIM + m] = val[r];
    } else {
        float* Es = Ws;
        __syncthreads();
        #pragma unroll
        for (int r = 0; r < 8; r++) Es[(r0 + r) * 132 + m] = val[r];
        __syncthreads();
        #pragma unroll
        for (int it = 0; it < 2; it++) {
            int idx = t + it * 512;
            int g = idx >> 5, kl = idx & 31;
            float4 o = *(const float4*)&Es[kl * 132 + g * 4];
            *(float4*)&g_Ec4[((size_t)(b * 32 + g) * DD + d0 + kl) * 4] = o;
        }
    }
}

// ---------------------------------------------------------------------------
// Kernel 2 (PDL secondary): grid = 2048 (8b x 64jg x 4kt), 64 threads,
// occ 16. Thread = 1 k, 4 j; f32x2 lanes packed over ADJACENT M:
// Ec / v / Ea pairs all arrive as naturally-aligned register pairs
// (zero dup2/vD). 8 m per iteration, 4-deep rational combine per lane
// (1 rcp-instr per 4 m). Epilogue: lane-sum + direct coalesced STG.32.
// ---------------------------------------------------------------------------
__global__ void __launch_bounds__(64, 16) k2_pairwise(
    const float* __restrict__ v,
    float* __restrict__ out)
{
    __shared__ __align__(16) float EaS[4 * DIM];   // [j][m] row-major
    __shared__ __align__(16) float vS[DIM];

    const int t   = threadIdx.x;
    const int bid = blockIdx.x;
    const int kt  = bid & 3;
    const int jg  = (bid >> 2) & 63;
    const int b   = bid >> 8;
    const int j0  = jg * 4;
    const int k   = kt * 64 + t;

    // k1-independent prologue (overlaps k1 under PDL)
    vS[t]      = v[t];
    vS[t + 64] = v[t + 64];

    cudaGridDependencySynchronize();

    // Stage 4 Ea rows (row-major, coalesced LDG.128 + linear STS.128)
    #pragma unroll
    for (int i = 0; i < 2; i++) {
        int idx = t + i * 64;              // 128 float4
        int j = idx >> 5, q = idx & 31;
        ((float4*)EaS)[idx] =
            ((const float4*)(g_Ea + (size_t)(b * DD + j0 + j) * DIM))[q];
    }
    __syncthreads();

    const float Vsum = g_Vsum;
    const ull ONE2 = dup2(1.0f);
    ull acc0 = dup2(0.0f), acc1 = dup2(0.0f);
    ull acc2 = dup2(0.0f), acc3 = dup2(0.0f);

    // Ec stream: ulonglong2 = one m-quad; consecutive quads DD apart.
    const ulonglong2* ecq =
        (const ulonglong2*)(g_Ec4 + (size_t)b * 32 * DD * 4 + k * 4);
    ulonglong2 E0 = ecq[0];
    ulonglong2 E1 = ecq[DD];

    #pragma unroll 2
    for (int gg = 0; gg < 16; gg++) {      // 8 m per iteration
        ulonglong2 N0 = __ldg(ecq + (size_t)(2 * gg + 2) * DD);  // padded tail
        ulonglong2 N1 = __ldg(ecq + (size_t)(2 * gg + 3) * DD);

        ulonglong2 vA = *(const ulonglong2*)&vS[8 * gg];      // (v01),(v23)
        ulonglong2 vB = *(const ulonglong2*)&vS[8 * gg + 4];  // (v45),(v67)

        #pragma unroll
        for (int j = 0; j < 4; j++) {
            ulonglong2 A0 = *(const ulonglong2*)&EaS[j * DIM + 8 * gg];
            ulonglong2 A1 = *(const ulonglong2*)&EaS[j * DIM + 8 * gg + 4];
            ull q01 = fma2(A0.x, E0.x, ONE2);
            ull q23 = fma2(A0.y, E0.y, ONE2);
            ull q45 = fma2(A1.x, E1.x, ONE2);
            ull q67 = fma2(A1.y, E1.y, ONE2);
            ull d03 = mul2(q01, q23);
            ull d47 = mul2(q45, q67);
            ull n03 = mul2(vA.x, q23); n03 = fma2(vA.y, q01, n03);
            ull n47 = mul2(vB.x, q67); n47 = fma2(vB.y, q45, n47);
            ull den = mul2(d03, d47);
            ull num = mul2(n03, d47); num = fma2(n47, d03, num);
            float2 dd = unpk(den);
            ull rr = pk(frcp(dd.x), frcp(dd.y));     // 1 rcp-lane per 4 m
            if      (j == 0) acc0 = fma2(num, rr, acc0);
            else if (j == 1) acc1 = fma2(num, rr, acc1);
            else if (j == 2) acc2 = fma2(num, rr, acc2);
            else             acc3 = fma2(num, rr, acc3);
        }
        E0 = N0; E1 = N1;
    }

    // Epilogue: lane-sum + direct coalesced stores (lanes k consecutive)
    float* ob = out + (size_t)(b * DD + j0) * DD + k;
    float2 u0 = unpk(acc0), u1 = unpk(acc1), u2 = unpk(acc2), u3 = unpk(acc3);
    ob[0 * DD] = fmaf(-2.0f, u0.x + u0.y, Vsum);
    ob[1 * DD] = fmaf(-2.0f, u1.x + u1.y, Vsum);
    ob[2 * DD] = fmaf(-2.0f, u2.x + u2.y, Vsum);
    ob[3 * DD] = fmaf(-2.0f, u3.x + u3.y, Vsum);
}

// ---------------------------------------------------------------------------
extern "C" void kernel_launch(void* const* d_in, const int* in_sizes, int n_in,
                              void* d_out, int out_size)
{
    const float* X  = (const float*)d_in[0];
    const float* W1 = (const float*)d_in[1];
    const float* W2 = (const float*)d_in[2];
    const float* v  = (const float*)d_in[3];
    float* out      = (float*)d_out;

    cudaFuncSetAttribute(k1_gemm_exp,
                         cudaFuncAttributeMaxDynamicSharedMemorySize, K1_SMEM);

    k1_gemm_exp<<<128, 512, K1_SMEM>>>(X, W1, W2, v);

    cudaLaunchAttribute attr[1];
    attr[0].id = cudaLaunchAttributeProgrammaticStreamSerialization;
    attr[0].val.programmaticStreamSerializationAllowed = 1;
    cudaLaunchConfig_t cfg = {};
    cfg.gridDim  = dim3(2048, 1, 1);
    cfg.blockDim = dim3(64, 1, 1);
    cfg.dynamicSmemBytes = 0;
    cfg.stream = 0;
    cfg.attrs = attr;
    cfg.numAttrs = 1;
    cudaLaunchKernelEx(&cfg, k2_pairwise, v, out);
}

// round 10
// speedup vs baseline: 1.0920x; 1.0920x over previous
#include <cuda_runtime.h>

typedef unsigned long long ull;

// Problem: X[8,256,128], W1[128,128], W2[128,128], v[128] -> out[8,256,256]
#define BB   8
#define DD   256
#define DIM  128

// Scratch:
//  g_Ea  : [b*DD+d][m]  natural row-major (k2 stages rows coalesced)
//  g_Ec4 : [b][g=m/4][k][m%4]  (k2 streams float4 per m-quad per thread)
__device__ float g_Ea [BB * DD * DIM];
__device__ float g_Ec4[BB * 32 * DD * 4 + 5 * DD * 4];  // pad: prefetch overrun (4 quads)
__device__ float g_Vsum;

// ---- packed f32x2 helpers (Blackwell) --------------------------------------
__device__ __forceinline__ ull fma2(ull a, ull b, ull c) {
    ull d; asm("fma.rn.f32x2 %0,%1,%2,%3;" : "=l"(d) : "l"(a), "l"(b), "l"(c)); return d;
}
__device__ __forceinline__ ull mul2(ull a, ull b) {
    ull d; asm("mul.rn.f32x2 %0,%1,%2;" : "=l"(d) : "l"(a), "l"(b)); return d;
}
__device__ __forceinline__ ull dup2(float x) {
    ull d; asm("mov.b64 %0,{%1,%1};" : "=l"(d) : "f"(x)); return d;
}
__device__ __forceinline__ float2 unpk(ull a) {
    float2 r; asm("mov.b64 {%0,%1},%2;" : "=f"(r.x), "=f"(r.y) : "l"(a)); return r;
}
__device__ __forceinline__ ull pk(float x, float y) {
    ull d; asm("mov.b64 %0,{%1,%2};" : "=l"(d) : "f"(x), "f"(y)); return d;
}
__device__ __forceinline__ float frcp(float x) {
    float r; asm("rcp.approx.f32 %0,%1;" : "=f"(r) : "f"(x)); return r;
}

// ---------------------------------------------------------------------------
// Kernel 1: grid = 128 (64 tiles of 32 rows x 2 mats), 512 threads, 1/SM.
// FFMA2 main loop. mat 0: Ea row-major DIRECT (coalesced). mat 1: Ec via
// conflict-free smem transpose -> STG.128. Block 0 also computes g_Vsum.
// ---------------------------------------------------------------------------
#define W_STRIDE 132
#define K1_SMEM ((DIM * W_STRIDE + 32 * DIM) * 4)

__global__ void __launch_bounds__(512, 1) k1_gemm_exp(
    const float* __restrict__ X,
    const float* __restrict__ W1,
    const float* __restrict__ W2,
    const float* __restrict__ v)
{
    extern __shared__ float sm[];
    float* Ws = sm;                        // 128 x 132 (reused as Es for mat 1)
    float* Xs = sm + DIM * W_STRIDE;       // 32 x 128

    const int t       = threadIdx.x;
    const int mat     = blockIdx.x & 1;
    const int rowbase = (blockIdx.x >> 1) * 32;
    const float* W = mat ? W2 : W1;

    if (blockIdx.x == 0 && t < 32) {       // Vsum side-job
        float s = v[t] + v[t + 32] + v[t + 64] + v[t + 96];
        #pragma unroll
        for (int o = 16; o; o >>= 1) s += __shfl_xor_sync(0xffffffffu, s, o);
        if (t == 0) g_Vsum = s;
    }

    #pragma unroll
    for (int i = t; i < DIM * 32; i += 512) {
        int m  = i >> 5;
        int k4 = i & 31;
        *(float4*)&Ws[m * W_STRIDE + k4 * 4] = ((const float4*)W)[i];
    }
    #pragma unroll
    for (int i = t; i < 1024; i += 512)
        ((float4*)Xs)[i] = ((const float4*)X)[rowbase * 32 + i];
    __syncthreads();

    const int m  = t & 127;
    const int r0 = (t >> 7) * 8;

    ull acc[8];
    #pragma unroll
    for (int r = 0; r < 8; r++) acc[r] = dup2(0.0f);

    #pragma unroll 4
    for (int k4 = 0; k4 < 32; k4++) {
        ulonglong2 w = *(const ulonglong2*)&Ws[m * W_STRIDE + k4 * 4];
        #pragma unroll
        for (int r = 0; r < 8; r++) {
            ulonglong2 x = *(const ulonglong2*)&Xs[(r0 + r) * DIM + k4 * 4];
            acc[r] = fma2(w.x, x.x, acc[r]);
            acc[r] = fma2(w.y, x.y, acc[r]);
        }
    }

    float val[8];
    #pragma unroll
    for (int r = 0; r < 8; r++) {
        float2 a = unpk(acc[r]);
        val[r] = __expf(2.0f * (a.x + a.y));
    }

    cudaTriggerProgrammaticLaunchCompletion();

    const int b  = rowbase >> 8;
    const int d0 = rowbase & 255;

    if (mat == 0) {
        // natural row-major, lanes m consecutive -> coalesced STG.32
        #pragma unroll
        for (int r = 0; r < 8; r++)
            g_Ea[(size_t)(rowbase + r0 + r) * DIM + m] = val[r];
    } else {
        float* Es = Ws;
        __syncthreads();
        #pragma unroll
        for (int r = 0; r < 8; r++) Es[(r0 + r) * 132 + m] = val[r];
        __syncthreads();
        #pragma unroll
        for (int it = 0; it < 2; it++) {
            int idx = t + it * 512;
            int g = idx >> 5, kl = idx & 31;
            float4 o = *(const float4*)&Es[kl * 132 + g * 4];
            *(float4*)&g_Ec4[((size_t)(b * 32 + g) * DD + d0 + kl) * 4] = o;
        }
    }
}

// ---------------------------------------------------------------------------
// Kernel 2 (PDL secondary): grid = 1024 (8b x 64jg x 2kt), 128 threads,
// occ 7 (28 warps/SM, single smooth wave). Thread = 1 k, 4 j; f32x2 lanes
// packed over ADJACENT M (Ec/v/Ea pairs arrive as aligned register pairs:
// zero dup MOVs). Ec register pipeline 2 iterations (16 m) deep to cover
// L2 latency. 8 m per iteration; 1 rcp-instr per 4 m via rational combine.
// ---------------------------------------------------------------------------
__global__ void __launch_bounds__(128, 7) k2_pairwise(
    const float* __restrict__ v,
    float* __restrict__ out)
{
    __shared__ __align__(16) float EaS[4 * DIM];   // [j][m] row-major
    __shared__ __align__(16) float vS[DIM];

    const int t   = threadIdx.x;
    const int bid = blockIdx.x;
    const int kt  = bid & 1;
    const int jg  = (bid >> 1) & 63;
    const int b   = bid >> 7;
    const int j0  = jg * 4;
    const int k   = kt * 128 + t;

    // k1-independent prologue (overlaps k1 under PDL)
    vS[t] = v[t];

    cudaGridDependencySynchronize();

    // Stage 4 Ea rows (row-major, coalesced LDG.128 + linear STS.128)
    {
        int j = t >> 5, q = t & 31;        // 128 float4 in one shot
        ((float4*)EaS)[t] =
            ((const float4*)(g_Ea + (size_t)(b * DD + j0 + j) * DIM))[q];
    }
    __syncthreads();

    const float Vsum = g_Vsum;
    const ull ONE2 = dup2(1.0f);
    ull acc0 = dup2(0.0f), acc1 = dup2(0.0f);
    ull acc2 = dup2(0.0f), acc3 = dup2(0.0f);

    // Ec stream: ulonglong2 = one m-quad; consecutive quads DD apart.
    const ulonglong2* ecq =
        (const ulonglong2*)(g_Ec4 + (size_t)b * 32 * DD * 4 + k * 4);

    // 2-deep register pipeline: P0 = data for gg, P1 = data for gg+1.
    ulonglong2 P0a = __ldg(ecq + 0 * DD), P0b = __ldg(ecq + 1 * DD);
    ulonglong2 P1a = __ldg(ecq + 2 * DD), P1b = __ldg(ecq + 3 * DD);

    #pragma unroll 4
    for (int gg = 0; gg < 16; gg++) {      // 8 m per iteration
        // prefetch for gg+2 (padded tail: reads up to quad 35 < pad)
        ulonglong2 Na = __ldg(ecq + (size_t)(2 * gg + 4) * DD);
        ulonglong2 Nb = __ldg(ecq + (size_t)(2 * gg + 5) * DD);

        ulonglong2 vA = *(const ulonglong2*)&vS[8 * gg];      // (v01),(v23)
        ulonglong2 vB = *(const ulonglong2*)&vS[8 * gg + 4];  // (v45),(v67)

        #pragma unroll
        for (int j = 0; j < 4; j++) {
            ulonglong2 A0 = *(const ulonglong2*)&EaS[j * DIM + 8 * gg];
            ulonglong2 A1 = *(const ulonglong2*)&EaS[j * DIM + 8 * gg + 4];
            ull q01 = fma2(A0.x, P0a.x, ONE2);
            ull q23 = fma2(A0.y, P0a.y, ONE2);
            ull q45 = fma2(A1.x, P0b.x, ONE2);
            ull q67 = fma2(A1.y, P0b.y, ONE2);
            ull d03 = mul2(q01, q23);
            ull d47 = mul2(q45, q67);
            ull n03 = mul2(vA.x, q23); n03 = fma2(vA.y, q01, n03);
            ull n47 = mul2(vB.x, q67); n47 = fma2(vB.y, q45, n47);
            ull den = mul2(d03, d47);
            ull num = mul2(n03, d47); num = fma2(n47, d03, num);
            float2 dd = unpk(den);
            ull rr = pk(frcp(dd.x), frcp(dd.y));     // 1 rcp-lane per 4 m
            if      (j == 0) acc0 = fma2(num, rr, acc0);
            else if (j == 1) acc1 = fma2(num, rr, acc1);
            else if (j == 2) acc2 = fma2(num, rr, acc2);
            else             acc3 = fma2(num, rr, acc3);
        }
        P0a = P1a; P0b = P1b;
        P1a = Na;  P1b = Nb;
    }

    // Epilogue: lane-sum + direct coalesced stores (lanes k consecutive)
    float* ob = out + (size_t)(b * DD + j0) * DD + k;
    float2 u0 = unpk(acc0), u1 = unpk(acc1), u2 = unpk(acc2), u3 = unpk(acc3);
    ob[0 * DD] = fmaf(-2.0f, u0.x + u0.y, Vsum);
    ob[1 * DD] = fmaf(-2.0f, u1.x + u1.y, Vsum);
    ob[2 * DD] = fmaf(-2.0f, u2.x + u2.y, Vsum);
    ob[3 * DD] = fmaf(-2.0f, u3.x + u3.y, Vsum);
}

// ---------------------------------------------------------------------------
extern "C" void kernel_launch(void* const* d_in, const int* in_sizes, int n_in,
                              void* d_out, int out_size)
{
    const float* X  = (const float*)d_in[0];
    const float* W1 = (const float*)d_in[1];
    const float* W2 = (const float*)d_in[2];
    const float* v  = (const float*)d_in[3];
    float* out      = (float*)d_out;

    cudaFuncSetAttribute(k1_gemm_exp,
                         cudaFuncAttributeMaxDynamicSharedMemorySize, K1_SMEM);

    k1_gemm_exp<<<128, 512, K1_SMEM>>>(X, W1, W2, v);

    cudaLaunchAttribute attr[1];
    attr[0].id = cudaLaunchAttributeProgrammaticStreamSerialization;
    attr[0].val.programmaticStreamSerializationAllowed = 1;
    cudaLaunchConfig_t cfg = {};
    cfg.gridDim  = dim3(1024, 1, 1);
    cfg.blockDim = dim3(128, 1, 1);
    cfg.dynamicSmemBytes = 0;
    cfg.stream = 0;
    cfg.attrs = attr;
    cfg.numAttrs = 1;
    cudaLaunchKernelEx(&cfg, k2_pairwise, v, out);
}